// round 1
// baseline (speedup 1.0000x reference)
#include <cuda_runtime.h>
#include <cuda_bf16.h>
#include <math.h>

#define BSZ   2
#define SEQ   2048
#define HID   2048
#define NH    32
#define NG    8
#define HD    64
#define KVD   512          // NG*HD
#define MROWS 4096         // BSZ*SEQ

// ---------------- scratch (device globals; no allocation allowed) ----------
__device__ float g_q  [MROWS * HID];          // q linear
__device__ float g_k  [MROWS * KVD];          // k linear
__device__ float g_v  [MROWS * KVD];          // v linear
__device__ float g_qr [BSZ * NH * SEQ * HD];  // q rope'd, [b,h,s,d]
__device__ float g_kr [BSZ * NG * SEQ * HD];  // k rope'd, [b,g,s,d]
__device__ float g_vt [BSZ * NG * SEQ * HD];  // v transposed, [b,g,s,d]
__device__ float g_att[MROWS * HID];          // attention out, [b,s,h*d]

// ---------------- generic SGEMM: C[M,N] = A[M,K] @ W[N,K]^T + bias ---------
// 128x128 tile, K-step 8, 256 threads, 8x8 per-thread register tile.
__global__ __launch_bounds__(256) void sgemm_bias(
    const float* __restrict__ A, const float* __restrict__ W,
    const float* __restrict__ bias, float* __restrict__ C,
    int M, int N, int K)
{
    __shared__ float As[8][128];
    __shared__ float Bs[8][128];

    const int tid = threadIdx.x;
    const int tx  = tid & 15;      // 0..15
    const int ty  = tid >> 4;      // 0..15
    const int m0  = blockIdx.y * 128;
    const int n0  = blockIdx.x * 128;

    float acc[8][8];
#pragma unroll
    for (int i = 0; i < 8; i++)
#pragma unroll
        for (int j = 0; j < 8; j++) acc[i][j] = 0.f;

    const int lr = tid >> 1;           // 0..127
    const int lc = (tid & 1) * 4;      // 0 or 4
    const float* Aptr = A + (size_t)(m0 + lr) * K + lc;
    const float* Wptr = W + (size_t)(n0 + lr) * K + lc;

    for (int k = 0; k < K; k += 8) {
        float4 av = *(const float4*)(Aptr + k);
        float4 bv = *(const float4*)(Wptr + k);
        As[lc + 0][lr] = av.x; As[lc + 1][lr] = av.y;
        As[lc + 2][lr] = av.z; As[lc + 3][lr] = av.w;
        Bs[lc + 0][lr] = bv.x; Bs[lc + 1][lr] = bv.y;
        Bs[lc + 2][lr] = bv.z; Bs[lc + 3][lr] = bv.w;
        __syncthreads();

#pragma unroll
        for (int kk = 0; kk < 8; kk++) {
            float4 a0 = *(const float4*)&As[kk][ty * 4];
            float4 a1 = *(const float4*)&As[kk][64 + ty * 4];
            float4 b0 = *(const float4*)&Bs[kk][tx * 4];
            float4 b1 = *(const float4*)&Bs[kk][64 + tx * 4];
            float a[8] = {a0.x, a0.y, a0.z, a0.w, a1.x, a1.y, a1.z, a1.w};
            float b[8] = {b0.x, b0.y, b0.z, b0.w, b1.x, b1.y, b1.z, b1.w};
#pragma unroll
            for (int i = 0; i < 8; i++)
#pragma unroll
                for (int j = 0; j < 8; j++)
                    acc[i][j] = fmaf(a[i], b[j], acc[i][j]);
        }
        __syncthreads();
    }

#pragma unroll
    for (int i = 0; i < 8; i++) {
        int row = m0 + ((i < 4) ? (ty * 4 + i) : (64 + ty * 4 + i - 4));
#pragma unroll
        for (int j = 0; j < 8; j++) {
            int col = n0 + ((j < 4) ? (tx * 4 + j) : (64 + tx * 4 + j - 4));
            C[(size_t)row * N + col] = acc[i][j] + bias[col];
        }
    }
}

// ---------------- RoPE + transpose kernels ---------------------------------
__global__ void rope_q_kernel(const float* __restrict__ qlin,
                              const float* __restrict__ freqs,
                              float* __restrict__ qr)
{
    int idx = blockIdx.x * blockDim.x + threadIdx.x;   // B*S*NH*32
    if (idx >= BSZ * SEQ * NH * 32) return;
    int i = idx & 31;
    int h = (idx >> 5) & (NH - 1);
    int s = (idx >> 10) & (SEQ - 1);
    int b = idx >> 21;
    const float* src = qlin + (size_t)(b * SEQ + s) * HID + h * HD;
    float xe = src[2 * i], xo = src[2 * i + 1];
    float c  = freqs[s * HD + 2 * i];
    float sn = freqs[s * HD + 2 * i + 1];
    float* dst = qr + ((size_t)(b * NH + h) * SEQ + s) * HD;
    dst[2 * i]     = xe * c - xo * sn;
    dst[2 * i + 1] = xe * sn + xo * c;
}

__global__ void rope_k_kernel(const float* __restrict__ klin,
                              const float* __restrict__ freqs,
                              float* __restrict__ kr)
{
    int idx = blockIdx.x * blockDim.x + threadIdx.x;   // B*S*NG*32
    if (idx >= BSZ * SEQ * NG * 32) return;
    int i = idx & 31;
    int g = (idx >> 5) & (NG - 1);
    int s = (idx >> 8) & (SEQ - 1);
    int b = idx >> 19;
    const float* src = klin + (size_t)(b * SEQ + s) * KVD + g * HD;
    float xe = src[2 * i], xo = src[2 * i + 1];
    float c  = freqs[s * HD + 2 * i];
    float sn = freqs[s * HD + 2 * i + 1];
    float* dst = kr + ((size_t)(b * NG + g) * SEQ + s) * HD;
    dst[2 * i]     = xe * c - xo * sn;
    dst[2 * i + 1] = xe * sn + xo * c;
}

__global__ void transpose_v_kernel(const float* __restrict__ vlin,
                                   float* __restrict__ vt)
{
    int idx = blockIdx.x * blockDim.x + threadIdx.x;   // B*S*NG*HD
    if (idx >= BSZ * SEQ * NG * HD) return;
    int d = idx & (HD - 1);
    int g = (idx >> 6) & (NG - 1);
    int s = (idx >> 9) & (SEQ - 1);
    int b = idx >> 20;
    vt[((size_t)(b * NG + g) * SEQ + s) * HD + d] =
        vlin[(size_t)(b * SEQ + s) * KVD + g * HD + d];
}

// ---------------- flash attention (64x64 tiles, online softmax) ------------
// grid: (SEQ/64, B*NH), 256 threads. smem (dynamic):
//   Qst[64][64] (d-major), Kst[64][64] (d-major), Vs[64][64], Ss[64][64],
//   m_s[64], l_s[64], al_s[64]
#define ATT_SMEM ((4 * 4096 + 192) * 4)

__global__ __launch_bounds__(256) void flash_attn_kernel(
    const float* __restrict__ qr, const float* __restrict__ kr,
    const float* __restrict__ vt, float* __restrict__ att)
{
    extern __shared__ float sm[];
    float* Qst  = sm;                 // [d*64 + i]
    float* Kst  = sm + 4096;          // [d*64 + j]
    float* Vs   = sm + 8192;          // [j*64 + d]
    float* Ss   = sm + 12288;         // [i*64 + j]
    float* m_s  = sm + 16384;
    float* l_s  = m_s + 64;
    float* al_s = l_s + 64;

    const int tid = threadIdx.x;
    const int tx  = tid & 15;
    const int ty  = tid >> 4;
    const int qb  = blockIdx.x;       // 0..31
    const int bh  = blockIdx.y;       // 0..63
    const int b   = bh / NH;
    const int h   = bh % NH;
    const int g   = h / (NH / NG);    // h/4
    const int q0  = qb * 64;

    const float* Qbase = qr + ((size_t)(b * NH + h) * SEQ + q0) * HD;
    const float* Kbase = kr + (size_t)(b * NG + g) * SEQ * HD;
    const float* Vbase = vt + (size_t)(b * NG + g) * SEQ * HD;

    // load Q (transposed to d-major)
    for (int e = tid; e < 4096; e += 256) {
        int r = e >> 6, d = e & 63;
        Qst[d * 64 + r] = Qbase[r * HD + d];
    }
    if (tid < 64) { m_s[tid] = -1e30f; l_s[tid] = 0.f; }

    float oacc[4][4];
#pragma unroll
    for (int i = 0; i < 4; i++)
#pragma unroll
        for (int j = 0; j < 4; j++) oacc[i][j] = 0.f;

    const int nkb = qb + 1;           // causal: only key blocks <= query block
    for (int kb = 0; kb < nkb; kb++) {
        const int j0 = kb * 64;
        __syncthreads();
        // load K (d-major) and V (row-major)
        for (int e = tid; e < 4096; e += 256) {
            int r = e >> 6, d = e & 63;
            Kst[d * 64 + r] = Kbase[(size_t)(j0 + r) * HD + d];
        }
        for (int e = tid * 4; e < 4096; e += 1024)
            *(float4*)&Vs[e] = *(const float4*)&Vbase[(size_t)j0 * HD + e];
        __syncthreads();

        // GEMM1: S = Q K^T
        float sacc[4][4];
#pragma unroll
        for (int i = 0; i < 4; i++)
#pragma unroll
            for (int j = 0; j < 4; j++) sacc[i][j] = 0.f;

        for (int d = 0; d < 64; d++) {
            float4 a = *(const float4*)&Qst[d * 64 + ty * 4];
            float4 bb = *(const float4*)&Kst[d * 64 + tx * 4];
            float av[4] = {a.x, a.y, a.z, a.w};
            float bvv[4] = {bb.x, bb.y, bb.z, bb.w};
#pragma unroll
            for (int i = 0; i < 4; i++)
#pragma unroll
                for (int j = 0; j < 4; j++)
                    sacc[i][j] = fmaf(av[i], bvv[j], sacc[i][j]);
        }

        // scale + causal mask, write to smem
        const float scale = 0.125f;   // 1/sqrt(64)
#pragma unroll
        for (int i = 0; i < 4; i++) {
            int ig = q0 + ty * 4 + i;
#pragma unroll
            for (int j = 0; j < 4; j++) {
                int jg = j0 + tx * 4 + j;
                float v = sacc[i][j] * scale + ((jg <= ig) ? 0.f : -1e9f);
                Ss[(ty * 4 + i) * 64 + tx * 4 + j] = v;
            }
        }
        __syncthreads();

        // online softmax per row (one thread per row)
        if (tid < 64) {
            int i = tid;
            float m_old = m_s[i];
            float mx = m_old;
#pragma unroll 8
            for (int j = 0; j < 64; j++) mx = fmaxf(mx, Ss[i * 64 + j]);
            float alpha = __expf(m_old - mx);
            float lsum = 0.f;
#pragma unroll 8
            for (int j = 0; j < 64; j++) {
                float p = __expf(Ss[i * 64 + j] - mx);
                Ss[i * 64 + j] = p;
                lsum += p;
            }
            m_s[i]  = mx;
            l_s[i]  = l_s[i] * alpha + lsum;
            al_s[i] = alpha;
        }
        __syncthreads();

        // rescale O and accumulate P @ V
        float al[4];
#pragma unroll
        for (int i = 0; i < 4; i++) al[i] = al_s[ty * 4 + i];
#pragma unroll
        for (int i = 0; i < 4; i++)
#pragma unroll
            for (int j = 0; j < 4; j++) oacc[i][j] *= al[i];

        for (int j = 0; j < 64; j++) {
            float4 vv = *(const float4*)&Vs[j * 64 + tx * 4];
            float vvv[4] = {vv.x, vv.y, vv.z, vv.w};
            float p[4];
#pragma unroll
            for (int i = 0; i < 4; i++) p[i] = Ss[(ty * 4 + i) * 64 + j];
#pragma unroll
            for (int i = 0; i < 4; i++)
#pragma unroll
                for (int jd = 0; jd < 4; jd++)
                    oacc[i][jd] = fmaf(p[i], vvv[jd], oacc[i][jd]);
        }
    }

    // epilogue: normalize and store as [b, s, h*64 + d]
#pragma unroll
    for (int i = 0; i < 4; i++) {
        float inv = 1.f / l_s[ty * 4 + i];
        int srow = q0 + ty * 4 + i;
        float* dst = att + (size_t)(b * SEQ + srow) * HID + h * HD + tx * 4;
#pragma unroll
        for (int j = 0; j < 4; j++) dst[j] = oacc[i][j] * inv;
    }
}

// ---------------- launch ----------------------------------------------------
extern "C" void kernel_launch(void* const* d_in, const int* in_sizes, int n_in,
                              void* d_out, int out_size)
{
    const float* x     = (const float*)d_in[0];
    const float* freqs = (const float*)d_in[1];
    // d_in[2] = mask (unused; causal computed directly)
    const float* wq = (const float*)d_in[3];
    const float* bq = (const float*)d_in[4];
    const float* wk = (const float*)d_in[5];
    const float* bk = (const float*)d_in[6];
    const float* wv = (const float*)d_in[7];
    const float* bv = (const float*)d_in[8];
    const float* wo = (const float*)d_in[9];
    const float* bo = (const float*)d_in[10];
    float* out = (float*)d_out;

    float *pq, *pk, *pv, *pqr, *pkr, *pvt, *patt;
    cudaGetSymbolAddress((void**)&pq,   g_q);
    cudaGetSymbolAddress((void**)&pk,   g_k);
    cudaGetSymbolAddress((void**)&pv,   g_v);
    cudaGetSymbolAddress((void**)&pqr,  g_qr);
    cudaGetSymbolAddress((void**)&pkr,  g_kr);
    cudaGetSymbolAddress((void**)&pvt,  g_vt);
    cudaGetSymbolAddress((void**)&patt, g_att);

    cudaFuncSetAttribute(flash_attn_kernel,
                         cudaFuncAttributeMaxDynamicSharedMemorySize, ATT_SMEM);

    // projections
    sgemm_bias<<<dim3(HID / 128, MROWS / 128), 256>>>(x, wq, bq, pq, MROWS, HID, HID);
    sgemm_bias<<<dim3(KVD / 128, MROWS / 128), 256>>>(x, wk, bk, pk, MROWS, KVD, HID);
    sgemm_bias<<<dim3(KVD / 128, MROWS / 128), 256>>>(x, wv, bv, pv, MROWS, KVD, HID);

    // rope + transpose
    rope_q_kernel<<<(BSZ * SEQ * NH * 32) / 256, 256>>>(pq, freqs, pqr);
    rope_k_kernel<<<(BSZ * SEQ * NG * 32) / 256, 256>>>(pk, freqs, pkr);
    transpose_v_kernel<<<(BSZ * SEQ * NG * HD) / 256, 256>>>(pv, pvt);

    // attention
    flash_attn_kernel<<<dim3(SEQ / 64, BSZ * NH), 256, ATT_SMEM>>>(pqr, pkr, pvt, patt);

    // output projection
    sgemm_bias<<<dim3(HID / 128, MROWS / 128), 256>>>(patt, wo, bo, out, MROWS, HID, HID);
}

// round 3
// speedup vs baseline: 1.6821x; 1.6821x over previous
#include <cuda_runtime.h>
#include <cuda_bf16.h>
#include <math.h>
#include <stdint.h>

#define BSZ   2
#define SEQ   2048
#define HID   2048
#define NH    32
#define NG    8
#define HD    64
#define KVD   512
#define MROWS 4096

// ---------------- scratch ---------------------------------------------------
__device__ float g_q  [MROWS * HID];
__device__ float g_k  [MROWS * KVD];
__device__ float g_v  [MROWS * KVD];
__device__ float g_qr [BSZ * NH * SEQ * HD];
__device__ float g_kr [BSZ * NG * SEQ * HD];
__device__ float g_vt [BSZ * NG * SEQ * HD];
__device__ float g_att[MROWS * HID];

// ---------------- helpers ---------------------------------------------------
__device__ __forceinline__ void cp_async16(float* smem_ptr, const float* gptr) {
    uint32_t s = (uint32_t)__cvta_generic_to_shared(smem_ptr);
    asm volatile("cp.async.cg.shared.global [%0], [%1], 16;\n" :: "r"(s), "l"(gptr));
}
#define CP_COMMIT()  asm volatile("cp.async.commit_group;\n" ::: "memory")
#define CP_WAIT(n)   asm volatile("cp.async.wait_group %0;\n" :: "n"(n) : "memory")

#define MMA_TF32(Cc, Aa, Bb) asm volatile( \
    "mma.sync.aligned.m16n8k8.row.col.f32.tf32.tf32.f32 " \
    "{%0,%1,%2,%3},{%4,%5,%6,%7},{%8,%9},{%0,%1,%2,%3};\n" \
    : "+f"(Cc[0]), "+f"(Cc[1]), "+f"(Cc[2]), "+f"(Cc[3]) \
    : "r"(Aa[0]), "r"(Aa[1]), "r"(Aa[2]), "r"(Aa[3]), "r"(Bb[0]), "r"(Bb[1]))

__device__ __forceinline__ uint32_t f2tf(float x) {
    uint32_t r; asm("cvt.rna.tf32.f32 %0, %1;" : "=r"(r) : "f"(x)); return r;
}
// 3xTF32 split: x = hi + lo (hi = tf32(x), lo = tf32(x - hi))
__device__ __forceinline__ void split_tf32(float x, uint32_t& h, uint32_t& l) {
    h = f2tf(x);
    l = f2tf(x - __uint_as_float(h));
}

// ---------------- 3xTF32 GEMM: C[M,N] = A[M,K] @ W[N,K]^T + bias ------------
#define GLD  36
#define GTILE (128 * GLD)
#define GEMM_SMEM (2 * 2 * GTILE * 4)

__global__ __launch_bounds__(256, 1) void gemm_tf32(
    const float* __restrict__ A, const float* __restrict__ W,
    const float* __restrict__ bias, float* __restrict__ C,
    int M, int N, int K)
{
    extern __shared__ float sm[];
    const int tid  = threadIdx.x;
    const int lane = tid & 31;
    const int w    = tid >> 5;
    const int wm   = w >> 2;
    const int wn   = w & 3;
    const int m0   = blockIdx.y * 128;
    const int n0   = blockIdx.x * 128;

    float c[4][4][4];
#pragma unroll
    for (int mt = 0; mt < 4; mt++)
#pragma unroll
        for (int nt = 0; nt < 4; nt++)
#pragma unroll
            for (int i = 0; i < 4; i++) c[mt][nt][i] = 0.f;

    {
        float* As = sm;
        float* Ws = sm + GTILE;
#pragma unroll
        for (int j = 0; j < 4; j++) {
            int i = tid + j * 256;
            int r = i >> 3, c4 = i & 7;
            cp_async16(As + r * GLD + c4 * 4, A + (size_t)(m0 + r) * K + c4 * 4);
            cp_async16(Ws + r * GLD + c4 * 4, W + (size_t)(n0 + r) * K + c4 * 4);
        }
        CP_COMMIT();
    }

    const int NIT = K >> 5;
    for (int it = 0; it < NIT; it++) {
        int s = it & 1;
        if (it + 1 < NIT) {
            int s2 = s ^ 1;
            int k0 = (it + 1) << 5;
            float* As = sm + s2 * 2 * GTILE;
            float* Ws = As + GTILE;
#pragma unroll
            for (int j = 0; j < 4; j++) {
                int i = tid + j * 256;
                int r = i >> 3, c4 = i & 7;
                cp_async16(As + r * GLD + c4 * 4, A + (size_t)(m0 + r) * K + k0 + c4 * 4);
                cp_async16(Ws + r * GLD + c4 * 4, W + (size_t)(n0 + r) * K + k0 + c4 * 4);
            }
            CP_COMMIT();
            CP_WAIT(1);
        } else {
            CP_WAIT(0);
        }
        __syncthreads();

        const float* As = sm + s * 2 * GTILE;
        const float* Ws = As + GTILE;
#pragma unroll
        for (int kk = 0; kk < 4; kk++) {
            int cc = kk * 8 + (lane & 3);
            uint32_t bh[4][2], bl[4][2];
#pragma unroll
            for (int nt = 0; nt < 4; nt++) {
                int r = wn * 32 + nt * 8 + (lane >> 2);
                split_tf32(Ws[r * GLD + cc],     bh[nt][0], bl[nt][0]);
                split_tf32(Ws[r * GLD + cc + 4], bh[nt][1], bl[nt][1]);
            }
#pragma unroll
            for (int mt = 0; mt < 4; mt++) {
                int r = wm * 64 + mt * 16 + (lane >> 2);
                uint32_t ah[4], al[4];
                split_tf32(As[r * GLD + cc],           ah[0], al[0]);
                split_tf32(As[(r + 8) * GLD + cc],     ah[1], al[1]);
                split_tf32(As[r * GLD + cc + 4],       ah[2], al[2]);
                split_tf32(As[(r + 8) * GLD + cc + 4], ah[3], al[3]);
#pragma unroll
                for (int nt = 0; nt < 4; nt++) {
                    MMA_TF32(c[mt][nt], ah, bh[nt]);
                    MMA_TF32(c[mt][nt], ah, bl[nt]);
                    MMA_TF32(c[mt][nt], al, bh[nt]);
                }
            }
        }
        __syncthreads();
    }

#pragma unroll
    for (int mt = 0; mt < 4; mt++) {
#pragma unroll
        for (int nt = 0; nt < 4; nt++) {
            int row = m0 + wm * 64 + mt * 16 + (lane >> 2);
            int col = n0 + wn * 32 + nt * 8 + ((lane & 3) << 1);
            float2 bv = *(const float2*)&bias[col];
            float2 o0 = make_float2(c[mt][nt][0] + bv.x, c[mt][nt][1] + bv.y);
            float2 o1 = make_float2(c[mt][nt][2] + bv.x, c[mt][nt][3] + bv.y);
            *(float2*)&C[(size_t)row * N + col]       = o0;
            *(float2*)&C[(size_t)(row + 8) * N + col] = o1;
        }
    }
}

// ---------------- RoPE + transpose ------------------------------------------
__global__ void rope_q_kernel(const float* __restrict__ qlin,
                              const float* __restrict__ freqs,
                              float* __restrict__ qr)
{
    int idx = blockIdx.x * blockDim.x + threadIdx.x;
    if (idx >= BSZ * SEQ * NH * 32) return;
    int i = idx & 31;
    int h = (idx >> 5) & (NH - 1);
    int s = (idx >> 10) & (SEQ - 1);
    int b = idx >> 21;
    const float* src = qlin + (size_t)(b * SEQ + s) * HID + h * HD;
    float xe = src[2 * i], xo = src[2 * i + 1];
    float cc = freqs[s * HD + 2 * i];
    float sn = freqs[s * HD + 2 * i + 1];
    float* dst = qr + ((size_t)(b * NH + h) * SEQ + s) * HD;
    dst[2 * i]     = xe * cc - xo * sn;
    dst[2 * i + 1] = xe * sn + xo * cc;
}

__global__ void rope_k_kernel(const float* __restrict__ klin,
                              const float* __restrict__ freqs,
                              float* __restrict__ kr)
{
    int idx = blockIdx.x * blockDim.x + threadIdx.x;
    if (idx >= BSZ * SEQ * NG * 32) return;
    int i = idx & 31;
    int g = (idx >> 5) & (NG - 1);
    int s = (idx >> 8) & (SEQ - 1);
    int b = idx >> 19;
    const float* src = klin + (size_t)(b * SEQ + s) * KVD + g * HD;
    float xe = src[2 * i], xo = src[2 * i + 1];
    float cc = freqs[s * HD + 2 * i];
    float sn = freqs[s * HD + 2 * i + 1];
    float* dst = kr + ((size_t)(b * NG + g) * SEQ + s) * HD;
    dst[2 * i]     = xe * cc - xo * sn;
    dst[2 * i + 1] = xe * sn + xo * cc;
}

__global__ void transpose_v_kernel(const float* __restrict__ vlin,
                                   float* __restrict__ vt)
{
    int idx = blockIdx.x * blockDim.x + threadIdx.x;
    if (idx >= BSZ * SEQ * NG * HD) return;
    int d = idx & (HD - 1);
    int g = (idx >> 6) & (NG - 1);
    int s = (idx >> 9) & (SEQ - 1);
    int b = idx >> 20;
    vt[((size_t)(b * NG + g) * SEQ + s) * HD + d] =
        vlin[(size_t)(b * SEQ + s) * KVD + g * HD + d];
}

// ---------------- flash attention, 3xTF32 mma --------------------------------
#define LDA 72
#define ATT_SMEM ((128 * LDA + 64 * LDA + 64 * LDA) * 4)

__global__ __launch_bounds__(256, 1) void flash_attn_tc(
    const float* __restrict__ qr, const float* __restrict__ kr,
    const float* __restrict__ vt, float* __restrict__ att)
{
    extern __shared__ float sm[];
    float* Qs = sm;                     // [128][LDA], reused as Ps
    float* Ks = sm + 128 * LDA;
    float* Vs = Ks + 64 * LDA;

    const int tid  = threadIdx.x;
    const int lane = tid & 31;
    const int w    = tid >> 5;
    const int qb   = blockIdx.x;
    const int bh_  = blockIdx.y;
    const int b    = bh_ >> 5;
    const int h    = bh_ & 31;
    const int g    = h >> 2;
    const int q0   = qb * 128;

    const float* Qbase = qr + ((size_t)(b * NH + h) * SEQ + q0) * HD;
    const float* Kbase = kr + (size_t)(b * NG + g) * SEQ * HD;
    const float* Vbase = vt + (size_t)(b * NG + g) * SEQ * HD;

    for (int i = tid; i < 128 * 16; i += 256) {
        int r = i >> 4, c4 = i & 15;
        *(float4*)&Qs[r * LDA + c4 * 4] = *(const float4*)&Qbase[(size_t)r * HD + c4 * 4];
    }
    __syncthreads();

    // cache Q fragments, pre-split (hi/lo)
    uint32_t qh[8][4], ql[8][4];
    {
        int r  = w * 16 + (lane >> 2);
        int cb = lane & 3;
#pragma unroll
        for (int kk = 0; kk < 8; kk++) {
            split_tf32(Qs[r * LDA + kk * 8 + cb],           qh[kk][0], ql[kk][0]);
            split_tf32(Qs[(r + 8) * LDA + kk * 8 + cb],     qh[kk][1], ql[kk][1]);
            split_tf32(Qs[r * LDA + kk * 8 + cb + 4],       qh[kk][2], ql[kk][2]);
            split_tf32(Qs[(r + 8) * LDA + kk * 8 + cb + 4], qh[kk][3], ql[kk][3]);
        }
    }

    float oacc[8][4];
#pragma unroll
    for (int nt = 0; nt < 8; nt++)
#pragma unroll
        for (int i = 0; i < 4; i++) oacc[nt][i] = 0.f;

    float m0 = -1e30f, m1 = -1e30f, l0 = 0.f, l1 = 0.f;

    const int gq0 = q0 + w * 16 + (lane >> 2);
    const int gq1 = gq0 + 8;
    const float scale = 0.125f;

    const int nkb = 2 * qb + 2;
    for (int kb = 0; kb < nkb; kb++) {
        const int j0 = kb * 64;
        __syncthreads();
        for (int i = tid; i < 64 * 16; i += 256) {
            int r = i >> 4, c4 = i & 15;
            *(float4*)&Ks[r * LDA + c4 * 4] = *(const float4*)&Kbase[(size_t)(j0 + r) * HD + c4 * 4];
            *(float4*)&Vs[r * LDA + c4 * 4] = *(const float4*)&Vbase[(size_t)(j0 + r) * HD + c4 * 4];
        }
        __syncthreads();

        // ---- S = Q K^T, 3xTF32 ----
        float sacc[8][4];
#pragma unroll
        for (int nt = 0; nt < 8; nt++)
#pragma unroll
            for (int i = 0; i < 4; i++) sacc[nt][i] = 0.f;

#pragma unroll
        for (int kk = 0; kk < 8; kk++) {
            int cc = kk * 8 + (lane & 3);
#pragma unroll
            for (int nt = 0; nt < 8; nt++) {
                int r = nt * 8 + (lane >> 2);
                uint32_t bh2[2], bl2[2];
                split_tf32(Ks[r * LDA + cc],     bh2[0], bl2[0]);
                split_tf32(Ks[r * LDA + cc + 4], bh2[1], bl2[1]);
                MMA_TF32(sacc[nt], qh[kk], bh2);
                MMA_TF32(sacc[nt], qh[kk], bl2);
                MMA_TF32(sacc[nt], ql[kk], bh2);
            }
        }

        const int colb = j0 + ((lane & 3) << 1);
#pragma unroll
        for (int nt = 0; nt < 8; nt++) {
            int c0g = colb + nt * 8, c1g = c0g + 1;
            sacc[nt][0] = sacc[nt][0] * scale + ((c0g <= gq0) ? 0.f : -1e9f);
            sacc[nt][1] = sacc[nt][1] * scale + ((c1g <= gq0) ? 0.f : -1e9f);
            sacc[nt][2] = sacc[nt][2] * scale + ((c0g <= gq1) ? 0.f : -1e9f);
            sacc[nt][3] = sacc[nt][3] * scale + ((c1g <= gq1) ? 0.f : -1e9f);
        }

        float mx0 = -1e30f, mx1 = -1e30f;
#pragma unroll
        for (int nt = 0; nt < 8; nt++) {
            mx0 = fmaxf(mx0, fmaxf(sacc[nt][0], sacc[nt][1]));
            mx1 = fmaxf(mx1, fmaxf(sacc[nt][2], sacc[nt][3]));
        }
        mx0 = fmaxf(mx0, __shfl_xor_sync(0xffffffffu, mx0, 1));
        mx0 = fmaxf(mx0, __shfl_xor_sync(0xffffffffu, mx0, 2));
        mx1 = fmaxf(mx1, __shfl_xor_sync(0xffffffffu, mx1, 1));
        mx1 = fmaxf(mx1, __shfl_xor_sync(0xffffffffu, mx1, 2));

        float mn0 = fmaxf(m0, mx0), mn1 = fmaxf(m1, mx1);
        float al0 = __expf(m0 - mn0), al1 = __expf(m1 - mn1);
        m0 = mn0; m1 = mn1;

        float ls0 = 0.f, ls1 = 0.f;
#pragma unroll
        for (int nt = 0; nt < 8; nt++) {
            float p00 = __expf(sacc[nt][0] - mn0);
            float p01 = __expf(sacc[nt][1] - mn0);
            float p10 = __expf(sacc[nt][2] - mn1);
            float p11 = __expf(sacc[nt][3] - mn1);
            sacc[nt][0] = p00; sacc[nt][1] = p01;
            sacc[nt][2] = p10; sacc[nt][3] = p11;
            ls0 += p00 + p01; ls1 += p10 + p11;
        }
        ls0 += __shfl_xor_sync(0xffffffffu, ls0, 1);
        ls0 += __shfl_xor_sync(0xffffffffu, ls0, 2);
        ls1 += __shfl_xor_sync(0xffffffffu, ls1, 1);
        ls1 += __shfl_xor_sync(0xffffffffu, ls1, 2);
        l0 = l0 * al0 + ls0;
        l1 = l1 * al1 + ls1;

#pragma unroll
        for (int nt = 0; nt < 8; nt++) {
            oacc[nt][0] *= al0; oacc[nt][1] *= al0;
            oacc[nt][2] *= al1; oacc[nt][3] *= al1;
        }

        // ---- write P to smem (warp-private rows) ----
        {
            int r  = w * 16 + (lane >> 2);
            int cl = (lane & 3) << 1;
#pragma unroll
            for (int nt = 0; nt < 8; nt++) {
                *(float2*)&Qs[r * LDA + nt * 8 + cl]       = make_float2(sacc[nt][0], sacc[nt][1]);
                *(float2*)&Qs[(r + 8) * LDA + nt * 8 + cl] = make_float2(sacc[nt][2], sacc[nt][3]);
            }
        }
        __syncwarp();

        // ---- O += P V, 3xTF32 ----
        {
            int r  = w * 16 + (lane >> 2);
            int cb = lane & 3;
#pragma unroll
            for (int kk = 0; kk < 8; kk++) {
                uint32_t ah[4], al_[4];
                split_tf32(Qs[r * LDA + kk * 8 + cb],           ah[0], al_[0]);
                split_tf32(Qs[(r + 8) * LDA + kk * 8 + cb],     ah[1], al_[1]);
                split_tf32(Qs[r * LDA + kk * 8 + cb + 4],       ah[2], al_[2]);
                split_tf32(Qs[(r + 8) * LDA + kk * 8 + cb + 4], ah[3], al_[3]);
                int kr0 = kk * 8 + cb;
#pragma unroll
                for (int nt = 0; nt < 8; nt++) {
                    int n = nt * 8 + (lane >> 2);
                    uint32_t bh2[2], bl2[2];
                    split_tf32(Vs[kr0 * LDA + n],       bh2[0], bl2[0]);
                    split_tf32(Vs[(kr0 + 4) * LDA + n], bh2[1], bl2[1]);
                    MMA_TF32(oacc[nt], ah, bh2);
                    MMA_TF32(oacc[nt], ah, bl2);
                    MMA_TF32(oacc[nt], al_, bh2);
                }
            }
        }
        __syncwarp();
    }

    float inv0 = 1.f / l0, inv1 = 1.f / l1;
    int row0 = q0 + w * 16 + (lane >> 2);
    int cl   = (lane & 3) << 1;
#pragma unroll
    for (int nt = 0; nt < 8; nt++) {
        int col = h * HD + nt * 8 + cl;
        *(float2*)&att[(size_t)(b * SEQ + row0) * HID + col] =
            make_float2(oacc[nt][0] * inv0, oacc[nt][1] * inv0);
        *(float2*)&att[(size_t)(b * SEQ + row0 + 8) * HID + col] =
            make_float2(oacc[nt][2] * inv1, oacc[nt][3] * inv1);
    }
}

// ---------------- launch ----------------------------------------------------
extern "C" void kernel_launch(void* const* d_in, const int* in_sizes, int n_in,
                              void* d_out, int out_size)
{
    const float* x     = (const float*)d_in[0];
    const float* freqs = (const float*)d_in[1];
    const float* wq = (const float*)d_in[3];
    const float* bq = (const float*)d_in[4];
    const float* wk = (const float*)d_in[5];
    const float* bk = (const float*)d_in[6];
    const float* wv = (const float*)d_in[7];
    const float* bv = (const float*)d_in[8];
    const float* wo = (const float*)d_in[9];
    const float* bo = (const float*)d_in[10];
    float* out = (float*)d_out;

    float *pq, *pk, *pv, *pqr, *pkr, *pvt, *patt;
    cudaGetSymbolAddress((void**)&pq,   g_q);
    cudaGetSymbolAddress((void**)&pk,   g_k);
    cudaGetSymbolAddress((void**)&pv,   g_v);
    cudaGetSymbolAddress((void**)&pqr,  g_qr);
    cudaGetSymbolAddress((void**)&pkr,  g_kr);
    cudaGetSymbolAddress((void**)&pvt,  g_vt);
    cudaGetSymbolAddress((void**)&patt, g_att);

    cudaFuncSetAttribute(gemm_tf32,
                         cudaFuncAttributeMaxDynamicSharedMemorySize, GEMM_SMEM);
    cudaFuncSetAttribute(flash_attn_tc,
                         cudaFuncAttributeMaxDynamicSharedMemorySize, ATT_SMEM);

    gemm_tf32<<<dim3(HID / 128, MROWS / 128), 256, GEMM_SMEM>>>(x, wq, bq, pq, MROWS, HID, HID);
    gemm_tf32<<<dim3(KVD / 128, MROWS / 128), 256, GEMM_SMEM>>>(x, wk, bk, pk, MROWS, KVD, HID);
    gemm_tf32<<<dim3(KVD / 128, MROWS / 128), 256, GEMM_SMEM>>>(x, wv, bv, pv, MROWS, KVD, HID);

    rope_q_kernel<<<(BSZ * SEQ * NH * 32) / 256, 256>>>(pq, freqs, pqr);
    rope_k_kernel<<<(BSZ * SEQ * NG * 32) / 256, 256>>>(pk, freqs, pkr);
    transpose_v_kernel<<<(BSZ * SEQ * NG * HD) / 256, 256>>>(pv, pvt);

    flash_attn_tc<<<dim3(SEQ / 128, BSZ * NH), 256, ATT_SMEM>>>(pqr, pkr, pvt, patt);

    gemm_tf32<<<dim3(HID / 128, MROWS / 128), 256, GEMM_SMEM>>>(patt, wo, bo, out, MROWS, HID, HID);
}

// round 4
// speedup vs baseline: 2.9655x; 1.7630x over previous
#include <cuda_runtime.h>
#include <cuda_bf16.h>
#include <math.h>
#include <stdint.h>

#define BSZ   2
#define SEQ   2048
#define HID   2048
#define NH    32
#define NG    8
#define HD    64
#define KVD   512
#define MROWS 4096

// ---------------- scratch ---------------------------------------------------
__device__ __nv_bfloat16 s_x_hi [MROWS * HID];
__device__ __nv_bfloat16 s_x_lo [MROWS * HID];
__device__ __nv_bfloat16 s_wq_hi[HID * HID];
__device__ __nv_bfloat16 s_wq_lo[HID * HID];
__device__ __nv_bfloat16 s_wk_hi[KVD * HID];
__device__ __nv_bfloat16 s_wk_lo[KVD * HID];
__device__ __nv_bfloat16 s_wv_hi[KVD * HID];
__device__ __nv_bfloat16 s_wv_lo[KVD * HID];
__device__ __nv_bfloat16 s_wo_hi[HID * HID];
__device__ __nv_bfloat16 s_wo_lo[HID * HID];
__device__ float g_q  [MROWS * HID];
__device__ float g_k  [MROWS * KVD];
__device__ float g_v  [MROWS * KVD];
__device__ __nv_bfloat16 s_qr_hi[BSZ * NH * SEQ * HD];
__device__ __nv_bfloat16 s_qr_lo[BSZ * NH * SEQ * HD];
__device__ __nv_bfloat16 s_kr_hi[BSZ * NG * SEQ * HD];
__device__ __nv_bfloat16 s_kr_lo[BSZ * NG * SEQ * HD];
__device__ __nv_bfloat16 s_vt_hi[BSZ * NG * HD * SEQ];   // [b,g,d,s]
__device__ __nv_bfloat16 s_vt_lo[BSZ * NG * HD * SEQ];
__device__ float g_att[MROWS * HID];
__device__ __nv_bfloat16 s_at_hi[MROWS * HID];
__device__ __nv_bfloat16 s_at_lo[MROWS * HID];

// ---------------- helpers ---------------------------------------------------
__device__ __forceinline__ void cp_async16(void* smem_ptr, const void* gptr) {
    uint32_t s = (uint32_t)__cvta_generic_to_shared(smem_ptr);
    asm volatile("cp.async.cg.shared.global [%0], [%1], 16;\n" :: "r"(s), "l"(gptr));
}
#define CP_COMMIT()  asm volatile("cp.async.commit_group;\n" ::: "memory")
#define CP_WAIT(n)   asm volatile("cp.async.wait_group %0;\n" :: "n"(n) : "memory")

#define MMA_BF16(Cc, Aa, Bb) asm volatile( \
    "mma.sync.aligned.m16n8k16.row.col.f32.bf16.bf16.f32 " \
    "{%0,%1,%2,%3},{%4,%5,%6,%7},{%8,%9},{%0,%1,%2,%3};\n" \
    : "+f"(Cc[0]), "+f"(Cc[1]), "+f"(Cc[2]), "+f"(Cc[3]) \
    : "r"(Aa[0]), "r"(Aa[1]), "r"(Aa[2]), "r"(Aa[3]), "r"(Bb[0]), "r"(Bb[1]))

// pack two floats into bf16x2 hi + lo-residual words
__device__ __forceinline__ uint32_t pack2(float x0, float x1, uint32_t& lo_out) {
    __nv_bfloat16 h0 = __float2bfloat16(x0);
    __nv_bfloat16 h1 = __float2bfloat16(x1);
    __nv_bfloat16 l0 = __float2bfloat16(x0 - __bfloat162float(h0));
    __nv_bfloat16 l1 = __float2bfloat16(x1 - __bfloat162float(h1));
    __nv_bfloat162 H = __halves2bfloat162(h0, h1);
    __nv_bfloat162 L = __halves2bfloat162(l0, l1);
    lo_out = *(uint32_t*)&L;
    return *(uint32_t*)&H;
}

// ---------------- elementwise split fp32 -> bf16 hi/lo ----------------------
__global__ void split_kernel(const float* __restrict__ in,
                             __nv_bfloat16* __restrict__ hi,
                             __nv_bfloat16* __restrict__ lo, int n)
{
    int i = (blockIdx.x * blockDim.x + threadIdx.x) * 2;
    if (i >= n) return;
    float2 v = *(const float2*)&in[i];
    uint32_t lw, hw = pack2(v.x, v.y, lw);
    *(uint32_t*)&hi[i] = hw;
    *(uint32_t*)&lo[i] = lw;
}

// ---------------- 3x bf16-split GEMM: C = A[M,K] @ W[N,K]^T + bias ----------
#define LDG_   40                       // bf16 row stride (32 + 8 pad)
#define GSTAGE (4 * 128 * LDG_)         // elems per stage (Ah,Al,Wh,Wl)
#define GEMM_SMEM (2 * GSTAGE * 2)      // bytes

__global__ __launch_bounds__(256, 1) void gemm_bf16x3(
    const __nv_bfloat16* __restrict__ Ah, const __nv_bfloat16* __restrict__ Al,
    const __nv_bfloat16* __restrict__ Wh, const __nv_bfloat16* __restrict__ Wl,
    const float* __restrict__ bias, float* __restrict__ C,
    int M, int N, int K)
{
    extern __shared__ __nv_bfloat16 smb[];
    const int tid  = threadIdx.x;
    const int lane = tid & 31;
    const int w    = tid >> 5;
    const int wm   = w >> 2;
    const int wn   = w & 3;
    const int grp  = lane >> 2;
    const int tig  = lane & 3;
    const int m0   = blockIdx.y * 128;
    const int n0   = blockIdx.x * 128;

    float c[4][4][4];
#pragma unroll
    for (int mt = 0; mt < 4; mt++)
#pragma unroll
        for (int nt = 0; nt < 4; nt++)
#pragma unroll
            for (int i = 0; i < 4; i++) c[mt][nt][i] = 0.f;

#define G_LOAD_STAGE(sidx, k0) do {                                          \
    __nv_bfloat16* Ash_ = smb + (sidx) * GSTAGE;                             \
    __nv_bfloat16* Asl_ = Ash_ + 128 * LDG_;                                 \
    __nv_bfloat16* Wsh_ = Asl_ + 128 * LDG_;                                 \
    __nv_bfloat16* Wsl_ = Wsh_ + 128 * LDG_;                                 \
    _Pragma("unroll")                                                        \
    for (int j_ = 0; j_ < 2; j_++) {                                         \
        int cch_ = tid + j_ * 256;                                           \
        int r_   = cch_ >> 2;                                                \
        int off_ = (cch_ & 3) * 8;                                           \
        cp_async16(Ash_ + r_ * LDG_ + off_, Ah + (size_t)(m0 + r_) * K + (k0) + off_); \
        cp_async16(Asl_ + r_ * LDG_ + off_, Al + (size_t)(m0 + r_) * K + (k0) + off_); \
        cp_async16(Wsh_ + r_ * LDG_ + off_, Wh + (size_t)(n0 + r_) * K + (k0) + off_); \
        cp_async16(Wsl_ + r_ * LDG_ + off_, Wl + (size_t)(n0 + r_) * K + (k0) + off_); \
    }                                                                        \
    CP_COMMIT();                                                             \
} while (0)

    G_LOAD_STAGE(0, 0);

    const int NIT = K >> 5;
    for (int it = 0; it < NIT; it++) {
        int s = it & 1;
        if (it + 1 < NIT) {
            G_LOAD_STAGE(s ^ 1, (it + 1) << 5);
            CP_WAIT(1);
        } else {
            CP_WAIT(0);
        }
        __syncthreads();

        const __nv_bfloat16* Ash = smb + s * GSTAGE;
        const __nv_bfloat16* Asl = Ash + 128 * LDG_;
        const __nv_bfloat16* Wsh = Asl + 128 * LDG_;
        const __nv_bfloat16* Wsl = Wsh + 128 * LDG_;

#pragma unroll
        for (int kk = 0; kk < 2; kk++) {
            const int cc = kk * 16 + tig * 2;
            uint32_t bh[4][2], bl[4][2];
#pragma unroll
            for (int nt = 0; nt < 4; nt++) {
                int r = wn * 32 + nt * 8 + grp;
                bh[nt][0] = *(const uint32_t*)&Wsh[r * LDG_ + cc];
                bh[nt][1] = *(const uint32_t*)&Wsh[r * LDG_ + cc + 8];
                bl[nt][0] = *(const uint32_t*)&Wsl[r * LDG_ + cc];
                bl[nt][1] = *(const uint32_t*)&Wsl[r * LDG_ + cc + 8];
            }
#pragma unroll
            for (int mt = 0; mt < 4; mt++) {
                int r = wm * 64 + mt * 16 + grp;
                uint32_t ah[4], al[4];
                ah[0] = *(const uint32_t*)&Ash[r * LDG_ + cc];
                ah[1] = *(const uint32_t*)&Ash[(r + 8) * LDG_ + cc];
                ah[2] = *(const uint32_t*)&Ash[r * LDG_ + cc + 8];
                ah[3] = *(const uint32_t*)&Ash[(r + 8) * LDG_ + cc + 8];
                al[0] = *(const uint32_t*)&Asl[r * LDG_ + cc];
                al[1] = *(const uint32_t*)&Asl[(r + 8) * LDG_ + cc];
                al[2] = *(const uint32_t*)&Asl[r * LDG_ + cc + 8];
                al[3] = *(const uint32_t*)&Asl[(r + 8) * LDG_ + cc + 8];
#pragma unroll
                for (int nt = 0; nt < 4; nt++) {
                    MMA_BF16(c[mt][nt], ah, bh[nt]);
                    MMA_BF16(c[mt][nt], ah, bl[nt]);
                    MMA_BF16(c[mt][nt], al, bh[nt]);
                }
            }
        }
        __syncthreads();
    }

#pragma unroll
    for (int mt = 0; mt < 4; mt++) {
#pragma unroll
        for (int nt = 0; nt < 4; nt++) {
            int row = m0 + wm * 64 + mt * 16 + grp;
            int col = n0 + wn * 32 + nt * 8 + tig * 2;
            float2 bv = *(const float2*)&bias[col];
            *(float2*)&C[(size_t)row * N + col] =
                make_float2(c[mt][nt][0] + bv.x, c[mt][nt][1] + bv.y);
            *(float2*)&C[(size_t)(row + 8) * N + col] =
                make_float2(c[mt][nt][2] + bv.x, c[mt][nt][3] + bv.y);
        }
    }
}

// ---------------- RoPE (outputs bf16 hi/lo) ---------------------------------
__global__ void rope_q_split(const float* __restrict__ qlin,
                             const float* __restrict__ freqs,
                             __nv_bfloat16* __restrict__ qhi,
                             __nv_bfloat16* __restrict__ qlo)
{
    int idx = blockIdx.x * blockDim.x + threadIdx.x;
    if (idx >= BSZ * SEQ * NH * 32) return;
    int i = idx & 31;
    int h = (idx >> 5) & (NH - 1);
    int s = (idx >> 10) & (SEQ - 1);
    int b = idx >> 21;
    const float* src = qlin + (size_t)(b * SEQ + s) * HID + h * HD;
    float xe = src[2 * i], xo = src[2 * i + 1];
    float cc = freqs[s * HD + 2 * i];
    float sn = freqs[s * HD + 2 * i + 1];
    float re = xe * cc - xo * sn;
    float ro = xe * sn + xo * cc;
    size_t off = ((size_t)(b * NH + h) * SEQ + s) * HD + 2 * i;
    uint32_t lw, hw = pack2(re, ro, lw);
    *(uint32_t*)&qhi[off] = hw;
    *(uint32_t*)&qlo[off] = lw;
}

__global__ void rope_k_split(const float* __restrict__ klin,
                             const float* __restrict__ freqs,
                             __nv_bfloat16* __restrict__ khi,
                             __nv_bfloat16* __restrict__ klo)
{
    int idx = blockIdx.x * blockDim.x + threadIdx.x;
    if (idx >= BSZ * SEQ * NG * 32) return;
    int i = idx & 31;
    int g = (idx >> 5) & (NG - 1);
    int s = (idx >> 8) & (SEQ - 1);
    int b = idx >> 19;
    const float* src = klin + (size_t)(b * SEQ + s) * KVD + g * HD;
    float xe = src[2 * i], xo = src[2 * i + 1];
    float cc = freqs[s * HD + 2 * i];
    float sn = freqs[s * HD + 2 * i + 1];
    float re = xe * cc - xo * sn;
    float ro = xe * sn + xo * cc;
    size_t off = ((size_t)(b * NG + g) * SEQ + s) * HD + 2 * i;
    uint32_t lw, hw = pack2(re, ro, lw);
    *(uint32_t*)&khi[off] = hw;
    *(uint32_t*)&klo[off] = lw;
}

// V: [b,s,g*64+d] fp32  ->  [b,g,d,s] bf16 hi/lo (2 seq positions per thread)
__global__ void transpose_v_split(const float* __restrict__ vlin,
                                  __nv_bfloat16* __restrict__ vhi,
                                  __nv_bfloat16* __restrict__ vlo)
{
    int idx = blockIdx.x * blockDim.x + threadIdx.x;   // BSZ*NG*HD*SEQ/2
    if (idx >= BSZ * NG * HD * (SEQ / 2)) return;
    int s2 = idx & (SEQ / 2 - 1);
    int d  = (idx >> 10) & (HD - 1);
    int g  = (idx >> 16) & (NG - 1);
    int b  = idx >> 19;
    int s  = s2 * 2;
    float v0 = vlin[(size_t)(b * SEQ + s)     * KVD + g * HD + d];
    float v1 = vlin[(size_t)(b * SEQ + s + 1) * KVD + g * HD + d];
    size_t off = ((size_t)(b * NG + g) * HD + d) * SEQ + s;
    uint32_t lw, hw = pack2(v0, v1, lw);
    *(uint32_t*)&vhi[off] = hw;
    *(uint32_t*)&vlo[off] = lw;
}

// ---------------- flash attention, bf16x3 mma --------------------------------
#define LDB_ 72
// Q/P: 2*128*72, K: 2*64*72, V: 2*64*72 bf16
#define ATT_SMEM ((2 * 128 * LDB_ + 4 * 64 * LDB_) * 2)

__global__ __launch_bounds__(256, 1) void flash_attn_bf16(
    const __nv_bfloat16* __restrict__ qhi, const __nv_bfloat16* __restrict__ qlo,
    const __nv_bfloat16* __restrict__ khi, const __nv_bfloat16* __restrict__ klo,
    const __nv_bfloat16* __restrict__ vhi, const __nv_bfloat16* __restrict__ vlo,
    float* __restrict__ att)
{
    extern __shared__ __nv_bfloat16 smb[];
    __nv_bfloat16* Qh = smb;                    // [128][LDB_], reused for P
    __nv_bfloat16* Ql = Qh + 128 * LDB_;
    __nv_bfloat16* Kh = Ql + 128 * LDB_;        // [64][LDB_]
    __nv_bfloat16* Kl = Kh + 64 * LDB_;
    __nv_bfloat16* Vh = Kl + 64 * LDB_;         // [64][LDB_]  (V^T: [d][s])
    __nv_bfloat16* Vl = Vh + 64 * LDB_;

    const int tid  = threadIdx.x;
    const int lane = tid & 31;
    const int w    = tid >> 5;
    const int grp  = lane >> 2;
    const int tig  = lane & 3;
    const int qb   = blockIdx.x;
    const int bh_  = blockIdx.y;
    const int b    = bh_ >> 5;
    const int h    = bh_ & 31;
    const int g    = h >> 2;
    const int q0   = qb * 128;
    const size_t qoff  = ((size_t)(b * NH + h) * SEQ + q0) * HD;
    const size_t kvoff = (size_t)(b * NG + g) * SEQ * HD;    // for K [s][d]
    const size_t vtoff = (size_t)(b * NG + g) * HD * SEQ;    // for V^T [d][s]

    // ---- load Q tile (128 x 64 bf16, hi+lo) ----
    for (int i = tid; i < 1024; i += 256) {
        int r = i >> 3, off = (i & 7) * 8;
        *(uint4*)&Qh[r * LDB_ + off] = *(const uint4*)&qhi[qoff + (size_t)r * HD + off];
        *(uint4*)&Ql[r * LDB_ + off] = *(const uint4*)&qlo[qoff + (size_t)r * HD + off];
    }
    __syncthreads();

    // ---- cache Q fragments ----
    uint32_t qfh[4][4], qfl[4][4];
    {
        int r = w * 16 + grp;
#pragma unroll
        for (int kk = 0; kk < 4; kk++) {
            int cc = kk * 16 + tig * 2;
            qfh[kk][0] = *(const uint32_t*)&Qh[r * LDB_ + cc];
            qfh[kk][1] = *(const uint32_t*)&Qh[(r + 8) * LDB_ + cc];
            qfh[kk][2] = *(const uint32_t*)&Qh[r * LDB_ + cc + 8];
            qfh[kk][3] = *(const uint32_t*)&Qh[(r + 8) * LDB_ + cc + 8];
            qfl[kk][0] = *(const uint32_t*)&Ql[r * LDB_ + cc];
            qfl[kk][1] = *(const uint32_t*)&Ql[(r + 8) * LDB_ + cc];
            qfl[kk][2] = *(const uint32_t*)&Ql[r * LDB_ + cc + 8];
            qfl[kk][3] = *(const uint32_t*)&Ql[(r + 8) * LDB_ + cc + 8];
        }
    }

    float oacc[8][4];
#pragma unroll
    for (int nt = 0; nt < 8; nt++)
#pragma unroll
        for (int i = 0; i < 4; i++) oacc[nt][i] = 0.f;

    float m0 = -1e30f, m1 = -1e30f, l0 = 0.f, l1 = 0.f;
    const int gq0 = q0 + w * 16 + grp;
    const int gq1 = gq0 + 8;
    const float scale = 0.125f;

    const int nkb = 2 * qb + 2;
    for (int kb = 0; kb < nkb; kb++) {
        const int j0 = kb * 64;
        __syncthreads();
        // K tile: [key][d] from khi/klo; V tile: [d][key] from vhi/vlo
        for (int i = tid; i < 512; i += 256) {
            int r = i >> 3, off = (i & 7) * 8;
            *(uint4*)&Kh[r * LDB_ + off] = *(const uint4*)&khi[kvoff + (size_t)(j0 + r) * HD + off];
            *(uint4*)&Kl[r * LDB_ + off] = *(const uint4*)&klo[kvoff + (size_t)(j0 + r) * HD + off];
            *(uint4*)&Vh[r * LDB_ + off] = *(const uint4*)&vhi[vtoff + (size_t)r * SEQ + j0 + off];
            *(uint4*)&Vl[r * LDB_ + off] = *(const uint4*)&vlo[vtoff + (size_t)r * SEQ + j0 + off];
        }
        __syncthreads();

        // ---- S = Q K^T ----
        float sacc[8][4];
#pragma unroll
        for (int nt = 0; nt < 8; nt++)
#pragma unroll
            for (int i = 0; i < 4; i++) sacc[nt][i] = 0.f;

#pragma unroll
        for (int kk = 0; kk < 4; kk++) {
            int cc = kk * 16 + tig * 2;
#pragma unroll
            for (int nt = 0; nt < 8; nt++) {
                int r = nt * 8 + grp;
                uint32_t bh2[2], bl2[2];
                bh2[0] = *(const uint32_t*)&Kh[r * LDB_ + cc];
                bh2[1] = *(const uint32_t*)&Kh[r * LDB_ + cc + 8];
                bl2[0] = *(const uint32_t*)&Kl[r * LDB_ + cc];
                bl2[1] = *(const uint32_t*)&Kl[r * LDB_ + cc + 8];
                MMA_BF16(sacc[nt], qfh[kk], bh2);
                MMA_BF16(sacc[nt], qfh[kk], bl2);
                MMA_BF16(sacc[nt], qfl[kk], bh2);
            }
        }

        // ---- scale + causal mask ----
        const int colb = j0 + tig * 2;
#pragma unroll
        for (int nt = 0; nt < 8; nt++) {
            int c0g = colb + nt * 8, c1g = c0g + 1;
            sacc[nt][0] = sacc[nt][0] * scale + ((c0g <= gq0) ? 0.f : -1e9f);
            sacc[nt][1] = sacc[nt][1] * scale + ((c1g <= gq0) ? 0.f : -1e9f);
            sacc[nt][2] = sacc[nt][2] * scale + ((c0g <= gq1) ? 0.f : -1e9f);
            sacc[nt][3] = sacc[nt][3] * scale + ((c1g <= gq1) ? 0.f : -1e9f);
        }

        // ---- online softmax ----
        float mx0 = -1e30f, mx1 = -1e30f;
#pragma unroll
        for (int nt = 0; nt < 8; nt++) {
            mx0 = fmaxf(mx0, fmaxf(sacc[nt][0], sacc[nt][1]));
            mx1 = fmaxf(mx1, fmaxf(sacc[nt][2], sacc[nt][3]));
        }
        mx0 = fmaxf(mx0, __shfl_xor_sync(0xffffffffu, mx0, 1));
        mx0 = fmaxf(mx0, __shfl_xor_sync(0xffffffffu, mx0, 2));
        mx1 = fmaxf(mx1, __shfl_xor_sync(0xffffffffu, mx1, 1));
        mx1 = fmaxf(mx1, __shfl_xor_sync(0xffffffffu, mx1, 2));

        float mn0 = fmaxf(m0, mx0), mn1 = fmaxf(m1, mx1);
        float al0 = __expf(m0 - mn0), al1 = __expf(m1 - mn1);
        m0 = mn0; m1 = mn1;

        float ls0 = 0.f, ls1 = 0.f;
#pragma unroll
        for (int nt = 0; nt < 8; nt++) {
            float p00 = __expf(sacc[nt][0] - mn0);
            float p01 = __expf(sacc[nt][1] - mn0);
            float p10 = __expf(sacc[nt][2] - mn1);
            float p11 = __expf(sacc[nt][3] - mn1);
            sacc[nt][0] = p00; sacc[nt][1] = p01;
            sacc[nt][2] = p10; sacc[nt][3] = p11;
            ls0 += p00 + p01; ls1 += p10 + p11;
        }
        ls0 += __shfl_xor_sync(0xffffffffu, ls0, 1);
        ls0 += __shfl_xor_sync(0xffffffffu, ls0, 2);
        ls1 += __shfl_xor_sync(0xffffffffu, ls1, 1);
        ls1 += __shfl_xor_sync(0xffffffffu, ls1, 2);
        l0 = l0 * al0 + ls0;
        l1 = l1 * al1 + ls1;

#pragma unroll
        for (int nt = 0; nt < 8; nt++) {
            oacc[nt][0] *= al0; oacc[nt][1] *= al0;
            oacc[nt][2] *= al1; oacc[nt][3] *= al1;
        }

        // ---- split P into bf16 hi/lo, store to smem (warp-private rows) ----
        {
            int pr = w * 16 + grp;
#pragma unroll
            for (int nt = 0; nt < 8; nt++) {
                int pc = nt * 8 + tig * 2;
                uint32_t lw0, hw0 = pack2(sacc[nt][0], sacc[nt][1], lw0);
                uint32_t lw1, hw1 = pack2(sacc[nt][2], sacc[nt][3], lw1);
                *(uint32_t*)&Qh[pr * LDB_ + pc]       = hw0;
                *(uint32_t*)&Ql[pr * LDB_ + pc]       = lw0;
                *(uint32_t*)&Qh[(pr + 8) * LDB_ + pc] = hw1;
                *(uint32_t*)&Ql[(pr + 8) * LDB_ + pc] = lw1;
            }
        }
        __syncwarp();

        // ---- O += P V ----
        {
            int pr = w * 16 + grp;
#pragma unroll
            for (int kk = 0; kk < 4; kk++) {
                int cc = kk * 16 + tig * 2;
                uint32_t ah[4], al_[4];
                ah[0]  = *(const uint32_t*)&Qh[pr * LDB_ + cc];
                ah[1]  = *(const uint32_t*)&Qh[(pr + 8) * LDB_ + cc];
                ah[2]  = *(const uint32_t*)&Qh[pr * LDB_ + cc + 8];
                ah[3]  = *(const uint32_t*)&Qh[(pr + 8) * LDB_ + cc + 8];
                al_[0] = *(const uint32_t*)&Ql[pr * LDB_ + cc];
                al_[1] = *(const uint32_t*)&Ql[(pr + 8) * LDB_ + cc];
                al_[2] = *(const uint32_t*)&Ql[pr * LDB_ + cc + 8];
                al_[3] = *(const uint32_t*)&Ql[(pr + 8) * LDB_ + cc + 8];
#pragma unroll
                for (int nt = 0; nt < 8; nt++) {
                    int r = nt * 8 + grp;
                    uint32_t bh2[2], bl2[2];
                    bh2[0] = *(const uint32_t*)&Vh[r * LDB_ + cc];
                    bh2[1] = *(const uint32_t*)&Vh[r * LDB_ + cc + 8];
                    bl2[0] = *(const uint32_t*)&Vl[r * LDB_ + cc];
                    bl2[1] = *(const uint32_t*)&Vl[r * LDB_ + cc + 8];
                    MMA_BF16(oacc[nt], ah, bh2);
                    MMA_BF16(oacc[nt], ah, bl2);
                    MMA_BF16(oacc[nt], al_, bh2);
                }
            }
        }
        __syncwarp();
    }

    // ---- epilogue ----
    float inv0 = 1.f / l0, inv1 = 1.f / l1;
    int row0 = q0 + w * 16 + grp;
#pragma unroll
    for (int nt = 0; nt < 8; nt++) {
        int col = h * HD + nt * 8 + tig * 2;
        *(float2*)&att[(size_t)(b * SEQ + row0) * HID + col] =
            make_float2(oacc[nt][0] * inv0, oacc[nt][1] * inv0);
        *(float2*)&att[(size_t)(b * SEQ + row0 + 8) * HID + col] =
            make_float2(oacc[nt][2] * inv1, oacc[nt][3] * inv1);
    }
}

// ---------------- launch ----------------------------------------------------
extern "C" void kernel_launch(void* const* d_in, const int* in_sizes, int n_in,
                              void* d_out, int out_size)
{
    const float* x     = (const float*)d_in[0];
    const float* freqs = (const float*)d_in[1];
    const float* wq = (const float*)d_in[3];
    const float* bq = (const float*)d_in[4];
    const float* wk = (const float*)d_in[5];
    const float* bk = (const float*)d_in[6];
    const float* wv = (const float*)d_in[7];
    const float* bv = (const float*)d_in[8];
    const float* wo = (const float*)d_in[9];
    const float* bo = (const float*)d_in[10];
    float* out = (float*)d_out;

    __nv_bfloat16 *xh, *xl, *wqh, *wql, *wkh, *wkl, *wvh, *wvl, *woh, *wol;
    __nv_bfloat16 *qrh, *qrl, *krh, *krl, *vth, *vtl, *ath, *atl;
    float *pq, *pk, *pv, *patt;
    cudaGetSymbolAddress((void**)&xh,  s_x_hi);  cudaGetSymbolAddress((void**)&xl,  s_x_lo);
    cudaGetSymbolAddress((void**)&wqh, s_wq_hi); cudaGetSymbolAddress((void**)&wql, s_wq_lo);
    cudaGetSymbolAddress((void**)&wkh, s_wk_hi); cudaGetSymbolAddress((void**)&wkl, s_wk_lo);
    cudaGetSymbolAddress((void**)&wvh, s_wv_hi); cudaGetSymbolAddress((void**)&wvl, s_wv_lo);
    cudaGetSymbolAddress((void**)&woh, s_wo_hi); cudaGetSymbolAddress((void**)&wol, s_wo_lo);
    cudaGetSymbolAddress((void**)&qrh, s_qr_hi); cudaGetSymbolAddress((void**)&qrl, s_qr_lo);
    cudaGetSymbolAddress((void**)&krh, s_kr_hi); cudaGetSymbolAddress((void**)&krl, s_kr_lo);
    cudaGetSymbolAddress((void**)&vth, s_vt_hi); cudaGetSymbolAddress((void**)&vtl, s_vt_lo);
    cudaGetSymbolAddress((void**)&ath, s_at_hi); cudaGetSymbolAddress((void**)&atl, s_at_lo);
    cudaGetSymbolAddress((void**)&pq,   g_q);
    cudaGetSymbolAddress((void**)&pk,   g_k);
    cudaGetSymbolAddress((void**)&pv,   g_v);
    cudaGetSymbolAddress((void**)&patt, g_att);

    cudaFuncSetAttribute(gemm_bf16x3,
                         cudaFuncAttributeMaxDynamicSharedMemorySize, GEMM_SMEM);
    cudaFuncSetAttribute(flash_attn_bf16,
                         cudaFuncAttributeMaxDynamicSharedMemorySize, ATT_SMEM);

    // splits
    split_kernel<<<(MROWS * HID / 2 + 255) / 256, 256>>>(x,  xh,  xl,  MROWS * HID);
    split_kernel<<<(HID * HID / 2 + 255) / 256, 256>>>(wq, wqh, wql, HID * HID);
    split_kernel<<<(KVD * HID / 2 + 255) / 256, 256>>>(wk, wkh, wkl, KVD * HID);
    split_kernel<<<(KVD * HID / 2 + 255) / 256, 256>>>(wv, wvh, wvl, KVD * HID);
    split_kernel<<<(HID * HID / 2 + 255) / 256, 256>>>(wo, woh, wol, HID * HID);

    // projections
    gemm_bf16x3<<<dim3(HID / 128, MROWS / 128), 256, GEMM_SMEM>>>(xh, xl, wqh, wql, bq, pq, MROWS, HID, HID);
    gemm_bf16x3<<<dim3(KVD / 128, MROWS / 128), 256, GEMM_SMEM>>>(xh, xl, wkh, wkl, bk, pk, MROWS, KVD, HID);
    gemm_bf16x3<<<dim3(KVD / 128, MROWS / 128), 256, GEMM_SMEM>>>(xh, xl, wvh, wvl, bv, pv, MROWS, KVD, HID);

    // rope + transpose (emit bf16 hi/lo)
    rope_q_split<<<(BSZ * SEQ * NH * 32) / 256, 256>>>(pq, freqs, qrh, qrl);
    rope_k_split<<<(BSZ * SEQ * NG * 32) / 256, 256>>>(pk, freqs, krh, krl);
    transpose_v_split<<<(BSZ * NG * HD * (SEQ / 2)) / 256, 256>>>(pv, vth, vtl);

    // attention
    flash_attn_bf16<<<dim3(SEQ / 128, BSZ * NH), 256, ATT_SMEM>>>(qrh, qrl, krh, krl, vth, vtl, patt);

    // output projection
    split_kernel<<<(MROWS * HID / 2 + 255) / 256, 256>>>(patt, ath, atl, MROWS * HID);
    gemm_bf16x3<<<dim3(HID / 128, MROWS / 128), 256, GEMM_SMEM>>>(ath, atl, woh, wol, bo, out, MROWS, HID, HID);
}